// round 14
// baseline (speedup 1.0000x reference)
#include <cuda_runtime.h>
#include <cuda_bf16.h>
#include <math.h>

typedef unsigned long long u64;

#define B_   32
#define S_   197
#define D_   384
#define H_   6
#define HD_  64
#define HID_ 1024
#define SD_  75648           // S*D
#define BS_  6304            // B*S
#define BH_  192             // B*H
#define SHD_ 12608           // S*HD
#define SPLITK_ 197
#define KCH_ 384             // SD / SPLITK

// ---------------- scratch (static device globals) ----------------
__device__ float g_x[B_ * SD_];             // LN(images)
__device__ float g_qkv[3 * BH_ * SHD_];     // [mat][b*H+h][s*HD+e]
__device__ float g_skip[B_ * SD_];          // attn out + residual
__device__ float g_y[B_ * SD_];             // LN(skip)
__device__ float g_yT[SD_ * B_];            // transposed y
__device__ float g_part[SPLITK_ * B_ * HID_];
__device__ float g_hT[HID_ * B_];           // gelu(y@W1+b1), transposed

// ---------------- packed f32x2 helpers ----------------
__device__ __forceinline__ u64 pack2(float a, float b) {
    u64 u;
    asm("mov.b64 %0, {%1, %2};" : "=l"(u) : "r"(__float_as_uint(a)), "r"(__float_as_uint(b)));
    return u;
}
__device__ __forceinline__ float2 unpack2(u64 u) {
    unsigned int lo, hi;
    asm("mov.b64 {%0, %1}, %2;" : "=r"(lo), "=r"(hi) : "l"(u));
    return make_float2(__uint_as_float(lo), __uint_as_float(hi));
}
#define FMA2(d, a, b) asm("fma.rn.f32x2 %0, %1, %2, %0;" : "+l"(d) : "l"(a), "l"(b))

// ---------------- LayerNorm over a contiguous slab ----------------
__device__ __forceinline__ void ln_block(const float* __restrict__ in,
                                         float* __restrict__ out, int n) {
    double s = 0.0, s2 = 0.0;
    for (int i = threadIdx.x; i < n; i += blockDim.x) {
        float v = in[i];
        s  += (double)v;
        s2 += (double)v * (double)v;
    }
    __shared__ double rs[32], rs2[32];
    __shared__ float smu, srs;
    int lane = threadIdx.x & 31, wid = threadIdx.x >> 5;
#pragma unroll
    for (int o = 16; o; o >>= 1) {
        s  += __shfl_xor_sync(0xffffffffu, s, o);
        s2 += __shfl_xor_sync(0xffffffffu, s2, o);
    }
    if (lane == 0) { rs[wid] = s; rs2[wid] = s2; }
    __syncthreads();
    if (threadIdx.x == 0) {
        int nw = blockDim.x >> 5;
        double ts = 0.0, ts2 = 0.0;
        for (int i = 0; i < nw; i++) { ts += rs[i]; ts2 += rs2[i]; }
        double mu  = ts / n;
        double var = ts2 / n - mu * mu;
        smu = (float)mu;
        srs = rsqrtf((float)var + 1e-5f);
    }
    __syncthreads();
    float mu = smu, r = srs;
    for (int i = threadIdx.x; i < n; i += blockDim.x)
        out[i] = (in[i] - mu) * r;
}

__global__ void ln_img_k(const float* __restrict__ in) {
    ln_block(in + (size_t)blockIdx.x * SD_, g_x + (size_t)blockIdx.x * SD_, SD_);
}
__global__ void ln_skip_k() {
    ln_block(g_skip + (size_t)blockIdx.x * SD_, g_y + (size_t)blockIdx.x * SD_, SD_);
}
__global__ void ln_head_k() {
    float* p = g_qkv + (size_t)blockIdx.x * SHD_;
    ln_block(p, p, SHD_);
}

// ---------------- QKV projection ----------------
// out[mat][b,h,s,e] = sum_d x[b,s,d] * w[mat][h][d,e]
// Block: 128 m x 64 e, BK = 16, 256 threads, thread = 8m x 4e (f32x2 over e).
__global__ void qkv_k(const float* __restrict__ w1,
                      const float* __restrict__ w2,
                      const float* __restrict__ w3) {
    const int m0  = blockIdx.x * 128;
    const int h   = blockIdx.y;
    const int mat = blockIdx.z;
    const float* w = (mat == 0 ? w1 : (mat == 1 ? w2 : w3)) + (size_t)h * (D_ * HD_);
    __shared__ float2 xs[128 * 16];   // [mm][kk] duplicated pairs (v,v)
    __shared__ float  ws[16 * 64];    // [kk][e]
    const int tid = threadIdx.x;
    const int tr = tid >> 4, tc = tid & 15;
    u64 acc[8][2];
#pragma unroll
    for (int i = 0; i < 8; i++) { acc[i][0] = 0ull; acc[i][1] = 0ull; }

    for (int k0 = 0; k0 < D_; k0 += 16) {
        __syncthreads();
#pragma unroll
        for (int i = 0; i < 8; i++) {
            int id = tid + i * 256;
            int kk = id & 15, mm = id >> 4;
            int m = m0 + mm;
            float v = (m < BS_) ? g_x[(size_t)m * D_ + k0 + kk] : 0.f;
            xs[mm * 16 + kk] = make_float2(v, v);
        }
#pragma unroll
        for (int i = 0; i < 4; i++) {
            int id = tid + i * 256;
            int kk = id >> 6, e = id & 63;
            ws[id] = w[(size_t)(k0 + kk) * HD_ + e];
        }
        __syncthreads();
#pragma unroll
        for (int kk = 0; kk < 16; kk++) {
            u64 b0 = *(const u64*)(ws + kk * 64 + tc * 4);
            u64 b1 = *(const u64*)(ws + kk * 64 + tc * 4 + 2);
#pragma unroll
            for (int i = 0; i < 8; i++) {
                u64 a = *((const u64*)xs + (tr * 8 + i) * 16 + kk);
                FMA2(acc[i][0], a, b0);
                FMA2(acc[i][1], a, b1);
            }
        }
    }
#pragma unroll
    for (int i = 0; i < 8; i++) {
        int m = m0 + tr * 8 + i;
        if (m < BS_) {
            int bb = m / S_, s = m % S_;
            float* op = g_qkv + ((size_t)(mat * BH_) + bb * H_ + h) * SHD_ + s * HD_ + tc * 4;
            float2 lo = unpack2(acc[i][0]);
            float2 hi = unpack2(acc[i][1]);
            float4 rr; rr.x = lo.x; rr.y = lo.y; rr.z = hi.x; rr.w = hi.y;
            *(float4*)op = rr;
        }
    }
}

// ---------------- Fused attention per (b,h) ----------------
#define KP_ 68
#define ATTN_SMEM_FLOATS (2 * S_ * KP_ + 256 + 1024 + 32 + 32 + 4 + 4 + 1024)
#define ATTN_SMEM_BYTES  (ATTN_SMEM_FLOATS * 4)

__global__ void attn_k() {
    extern __shared__ float sm[];
    float* Ks     = sm;                       // S*KP
    float* Vs     = Ks + S_ * KP_;            // S*KP
    float* qs     = Vs + S_ * KP_;            // 256 : [r][e]
    float* ps     = qs + 256;                 // 1024: [t][r] interleaved (t*4+r)
    float* rmax   = ps + 1024;                // 32  : [r][wid]
    float* rsum   = rmax + 32;                // 32
    float* rowmax = rsum + 32;                // 4
    float* rowsum = rowmax + 4;               // 4
    float* obuf   = rowsum + 4;               // 1024: [part][r][e]

    const int bh  = blockIdx.x;
    const int tid = threadIdx.x;
    const int lane = tid & 31, wid = tid >> 5;
    const float* qg = g_qkv + (size_t)bh * SHD_;
    const float* kg = g_qkv + (size_t)(BH_ + bh) * SHD_;
    const float* vg = g_qkv + (size_t)(2 * BH_ + bh) * SHD_;

    for (int idx = tid; idx < SHD_; idx += 256) {
        int t = idx >> 6, e = idx & 63;
        Ks[t * KP_ + e] = kg[idx];
        Vs[t * KP_ + e] = vg[idx];
    }
    const int bb = bh / H_, hh = bh % H_;
    const float scale = rsqrtf((float)S_);
    const float* xres = g_x + (size_t)bb * SD_;
    float* outp = g_skip + (size_t)bb * SD_;

    for (int r0 = 0; r0 < S_; r0 += 4) {
        // load 4 query rows into qs[r*64+e]
        {
            int r = tid >> 6, e = tid & 63;
            int row = r0 + r;
            qs[tid] = (row < S_) ? qg[row * HD_ + e] : 0.f;
        }
        __syncthreads();

        // scores: thread tid = key index t
        float sc0 = -1e30f, sc1 = -1e30f, sc2 = -1e30f, sc3 = -1e30f;
        if (tid < S_) {
            const float4* kr = (const float4*)(Ks + tid * KP_);
            const float4* q4 = (const float4*)qs;
            float a0 = 0.f, a1 = 0.f, a2 = 0.f, a3 = 0.f;
#pragma unroll
            for (int ee = 0; ee < 16; ee++) {
                float4 kv = kr[ee];
                float4 v0 = q4[ee];
                float4 v1 = q4[16 + ee];
                float4 v2 = q4[32 + ee];
                float4 v3 = q4[48 + ee];
                a0 += kv.x * v0.x + kv.y * v0.y + kv.z * v0.z + kv.w * v0.w;
                a1 += kv.x * v1.x + kv.y * v1.y + kv.z * v1.z + kv.w * v1.w;
                a2 += kv.x * v2.x + kv.y * v2.y + kv.z * v2.z + kv.w * v2.w;
                a3 += kv.x * v3.x + kv.y * v3.y + kv.z * v3.z + kv.w * v3.w;
            }
            sc0 = a0 * scale; sc1 = a1 * scale; sc2 = a2 * scale; sc3 = a3 * scale;
        }
        // row maxima
        float m0 = sc0, m1 = sc1, m2 = sc2, m3 = sc3;
#pragma unroll
        for (int o = 16; o; o >>= 1) {
            m0 = fmaxf(m0, __shfl_xor_sync(0xffffffffu, m0, o));
            m1 = fmaxf(m1, __shfl_xor_sync(0xffffffffu, m1, o));
            m2 = fmaxf(m2, __shfl_xor_sync(0xffffffffu, m2, o));
            m3 = fmaxf(m3, __shfl_xor_sync(0xffffffffu, m3, o));
        }
        if (lane == 0) {
            rmax[0 * 8 + wid] = m0; rmax[1 * 8 + wid] = m1;
            rmax[2 * 8 + wid] = m2; rmax[3 * 8 + wid] = m3;
        }
        __syncthreads();
        if (tid < 4) {
            float mm = -1e30f;
#pragma unroll
            for (int wq = 0; wq < 8; wq++) mm = fmaxf(mm, rmax[tid * 8 + wq]);
            rowmax[tid] = mm;
        }
        __syncthreads();
        // exp + row sums; ps interleaved [t*4 + r]
        float e0 = 0.f, e1 = 0.f, e2 = 0.f, e3 = 0.f;
        if (tid < S_) {
            e0 = __expf(sc0 - rowmax[0]);
            e1 = __expf(sc1 - rowmax[1]);
            e2 = __expf(sc2 - rowmax[2]);
            e3 = __expf(sc3 - rowmax[3]);
        }
        *(float4*)(ps + tid * 4) = make_float4(e0, e1, e2, e3);
        float s0 = e0, s1 = e1, s2 = e2, s3 = e3;
#pragma unroll
        for (int o = 16; o; o >>= 1) {
            s0 += __shfl_xor_sync(0xffffffffu, s0, o);
            s1 += __shfl_xor_sync(0xffffffffu, s1, o);
            s2 += __shfl_xor_sync(0xffffffffu, s2, o);
            s3 += __shfl_xor_sync(0xffffffffu, s3, o);
        }
        if (lane == 0) {
            rsum[0 * 8 + wid] = s0; rsum[1 * 8 + wid] = s1;
            rsum[2 * 8 + wid] = s2; rsum[3 * 8 + wid] = s3;
        }
        __syncthreads();
        if (tid < 4) {
            float ss = 0.f;
#pragma unroll
            for (int wq = 0; wq < 8; wq++) ss += rsum[tid * 8 + wq];
            rowsum[tid] = ss;
        }
        __syncthreads();
        // AV: thread = (part 0..3, e 0..63), t strided by 4
        {
            int e = tid & 63, part = tid >> 6;
            float a0 = 0.f, a1 = 0.f, a2 = 0.f, a3 = 0.f;
            for (int t = part; t < S_; t += 4) {
                float vv = Vs[t * KP_ + e];
                float4 p = *(const float4*)(ps + t * 4);
                a0 += p.x * vv; a1 += p.y * vv; a2 += p.z * vv; a3 += p.w * vv;
            }
            obuf[part * 256 + e]       = a0;
            obuf[part * 256 + 64 + e]  = a1;
            obuf[part * 256 + 128 + e] = a2;
            obuf[part * 256 + 192 + e] = a3;
        }
        __syncthreads();
        // writeback with residual
        {
            int r = tid >> 6, e = tid & 63;
            int row = r0 + r;
            if (row < S_) {
                float o = obuf[r * 64 + e] + obuf[256 + r * 64 + e] +
                          obuf[512 + r * 64 + e] + obuf[768 + r * 64 + e];
                o /= rowsum[r];
                int off = row * D_ + hh * HD_ + e;
                outp[off] = o + xres[off];
            }
        }
        __syncthreads();
    }
}

// ---------------- transpose g_y -> g_yT ----------------
__global__ void transpose_k() {
    __shared__ float t[32][33];
    int k0 = blockIdx.x * 32;
    int tx = threadIdx.x & 31, ty = threadIdx.x >> 5;  // ty 0..7
#pragma unroll
    for (int i = 0; i < 4; i++) {
        int m = ty + 8 * i;
        t[m][tx] = g_y[(size_t)m * SD_ + k0 + tx];
    }
    __syncthreads();
#pragma unroll
    for (int i = 0; i < 4; i++) {
        int kk = ty + 8 * i;
        g_yT[(size_t)(k0 + kk) * 32 + tx] = t[tx][kk];
    }
}

// ---------------- MLP GEMM 1 (split-K partials) ----------------
// C[32,1024] = y[32,SD] @ W1[SD,1024], K-chunk 384 per blockIdx.y.
// Block tile 32m x 64n. Thread: nn=tid&31 owns n {nn, nn+32}; mg=tid>>5 owns m-pairs {2mg, 2mg+1}.
__global__ void mlp1_k(const float* __restrict__ w1) {
    const int n0 = blockIdx.x * 64;
    const int kbase = blockIdx.y * KCH_;
    __shared__ float  ws[16 * 64];
    __shared__ float2 xs[16 * 16];   // [kk][mpair]
    const int tid = threadIdx.x;
    const int nn = tid & 31;
    const int mg = tid >> 5;  // 0..7
    u64 acc[2][2] = {{0ull, 0ull}, {0ull, 0ull}};

    for (int k0 = 0; k0 < KCH_; k0 += 16) {
        __syncthreads();
#pragma unroll
        for (int i = 0; i < 4; i++) {
            int id = tid + i * 256;
            int kk = id >> 6, e = id & 63;
            ws[id] = w1[(size_t)(kbase + k0 + kk) * HID_ + n0 + e];
        }
        {
            int kk = tid >> 4, mp = tid & 15;
            xs[tid] = ((const float2*)g_yT)[(size_t)(kbase + k0 + kk) * 16 + mp];
        }
        __syncthreads();
#pragma unroll
        for (int kk = 0; kk < 16; kk++) {
            float w0 = ws[kk * 64 + nn];
            float w1v = ws[kk * 64 + 32 + nn];
            u64 b0 = pack2(w0, w0);
            u64 b1 = pack2(w1v, w1v);
            u64 a0 = *((const u64*)xs + kk * 16 + mg * 2);
            u64 a1 = *((const u64*)xs + kk * 16 + mg * 2 + 1);
            FMA2(acc[0][0], a0, b0);
            FMA2(acc[0][1], a1, b0);
            FMA2(acc[1][0], a0, b1);
            FMA2(acc[1][1], a1, b1);
        }
    }
    float* pp = g_part + (size_t)blockIdx.y * (B_ * HID_);
#pragma unroll
    for (int j = 0; j < 2; j++) {
        int n = n0 + nn + 32 * j;
#pragma unroll
        for (int i = 0; i < 2; i++) {
            float2 v = unpack2(acc[j][i]);
            int m = 2 * (mg * 2 + i);
            pp[(size_t)m * HID_ + n]       = v.x;
            pp[(size_t)(m + 1) * HID_ + n] = v.y;
        }
    }
}

// ---------------- reduce split-K + bias + GELU -> g_hT ----------------
__global__ void reduce1_k(const float* __restrict__ b1) {
    int idx = blockIdx.x * 256 + threadIdx.x;   // 0..32767
    float s = 0.f;
#pragma unroll 4
    for (int c = 0; c < SPLITK_; c++) s += g_part[(size_t)c * (B_ * HID_) + idx];
    int m = idx >> 10, j = idx & 1023;
    s += b1[j];
    float g = s * normcdff(s);
    g_hT[(size_t)j * 32 + m] = g;
}

// ---------------- MLP GEMM 2 + bias + GELU + skip ----------------
// out[32,SD] = skip + gelu(h[32,1024] @ W2[1024,SD] + b2)
// Block tile 32m x 128n. Thread: nn=tid&63 owns n {nn, nn+64}; mg=tid>>6 owns m-pairs mg*4..+3.
__global__ void mlp2_k(const float* __restrict__ w2, const float* __restrict__ b2,
                       float* __restrict__ out) {
    const int n0 = blockIdx.x * 128;
    __shared__ float  ws[16 * 128];
    __shared__ float2 xs[16 * 16];
    const int tid = threadIdx.x;
    const int nn = tid & 63;
    const int mg = tid >> 6;  // 0..3
    u64 acc[2][4];
#pragma unroll
    for (int j = 0; j < 2; j++)
#pragma unroll
        for (int i = 0; i < 4; i++) acc[j][i] = 0ull;

    for (int k0 = 0; k0 < HID_; k0 += 16) {
        __syncthreads();
#pragma unroll
        for (int i = 0; i < 8; i++) {
            int id = tid + i * 256;
            int kk = id >> 7, e = id & 127;
            ws[id] = w2[(size_t)(k0 + kk) * SD_ + n0 + e];
        }
        {
            int kk = tid >> 4, mp = tid & 15;
            xs[tid] = ((const float2*)g_hT)[(k0 + kk) * 16 + mp];
        }
        __syncthreads();
#pragma unroll
        for (int kk = 0; kk < 16; kk++) {
            float w0 = ws[kk * 128 + nn];
            float w1v = ws[kk * 128 + 64 + nn];
            u64 b0 = pack2(w0, w0);
            u64 b1 = pack2(w1v, w1v);
#pragma unroll
            for (int i = 0; i < 4; i++) {
                u64 a = *((const u64*)xs + kk * 16 + mg * 4 + i);
                FMA2(acc[0][i], a, b0);
                FMA2(acc[1][i], a, b1);
            }
        }
    }
#pragma unroll
    for (int j = 0; j < 2; j++) {
        int n = n0 + nn + 64 * j;
        float bias = b2[n];
#pragma unroll
        for (int i = 0; i < 4; i++) {
            float2 v = unpack2(acc[j][i]);
            int m = 2 * (mg * 4 + i);
            float s0 = v.x + bias, s1 = v.y + bias;
            float g0 = s0 * normcdff(s0);
            float g1 = s1 * normcdff(s1);
            out[(size_t)m * SD_ + n]       = g_skip[(size_t)m * SD_ + n] + g0;
            out[(size_t)(m + 1) * SD_ + n] = g_skip[(size_t)(m + 1) * SD_ + n] + g1;
        }
    }
}

// ---------------- launch ----------------
extern "C" void kernel_launch(void* const* d_in, const int* in_sizes, int n_in,
                              void* d_out, int out_size) {
    const float* images = (const float*)d_in[0];
    const float* w1     = (const float*)d_in[1];
    const float* w2     = (const float*)d_in[2];
    const float* w3     = (const float*)d_in[3];
    const float* mlp_w1 = (const float*)d_in[4];
    const float* mlp_b1 = (const float*)d_in[5];
    const float* mlp_w2 = (const float*)d_in[6];
    const float* mlp_b2 = (const float*)d_in[7];
    float* out = (float*)d_out;

    cudaFuncSetAttribute(attn_k, cudaFuncAttributeMaxDynamicSharedMemorySize,
                         ATTN_SMEM_BYTES);

    ln_img_k<<<B_, 512>>>(images);
    qkv_k<<<dim3(50, H_, 3), 256>>>(w1, w2, w3);
    ln_head_k<<<3 * BH_, 512>>>();
    attn_k<<<BH_, 256, ATTN_SMEM_BYTES>>>();
    ln_skip_k<<<B_, 512>>>();
    transpose_k<<<SD_ / 32, 256>>>();
    mlp1_k<<<dim3(HID_ / 64, SPLITK_), 256>>>(mlp_w1);
    reduce1_k<<<(B_ * HID_) / 256, 256>>>(mlp_b1);
    mlp2_k<<<SD_ / 128, 256>>>(mlp_w2, mlp_b2, out);
}

// round 15
// speedup vs baseline: 1.0146x; 1.0146x over previous
#include <cuda_runtime.h>
#include <cuda_bf16.h>
#include <math.h>

typedef unsigned long long u64;

#define B_   32
#define S_   197
#define D_   384
#define H_   6
#define HD_  64
#define HID_ 1024
#define SD_  75648           // S*D
#define BS_  6304            // B*S
#define BH_  192             // B*H
#define SHD_ 12608           // S*HD
#define SPLITK_ 197
#define KCH_ 384             // SD / SPLITK

// ---------------- scratch (static device globals) ----------------
__device__ float g_x[B_ * SD_];             // LN(images)
__device__ float g_qkv[3 * BH_ * SHD_];     // [mat][b*H+h][s*HD+e]
__device__ float g_skip[B_ * SD_];          // attn out + residual
__device__ float g_y[B_ * SD_];             // LN(skip)
__device__ float g_yT[SD_ * B_];            // transposed y
__device__ float g_part[SPLITK_ * B_ * HID_];
__device__ float g_hT[HID_ * B_];           // gelu(y@W1+b1), transposed

// ---------------- packed f32x2 helpers ----------------
__device__ __forceinline__ u64 pack2(float a, float b) {
    u64 u;
    asm("mov.b64 %0, {%1, %2};" : "=l"(u) : "r"(__float_as_uint(a)), "r"(__float_as_uint(b)));
    return u;
}
__device__ __forceinline__ float2 unpack2(u64 u) {
    unsigned int lo, hi;
    asm("mov.b64 {%0, %1}, %2;" : "=r"(lo), "=r"(hi) : "l"(u));
    return make_float2(__uint_as_float(lo), __uint_as_float(hi));
}
#define FMA2(d, a, b) asm("fma.rn.f32x2 %0, %1, %2, %0;" : "+l"(d) : "l"(a), "l"(b))

// ---------------- LayerNorm over a contiguous slab ----------------
__device__ __forceinline__ void ln_block(const float* __restrict__ in,
                                         float* __restrict__ out, int n) {
    double s = 0.0, s2 = 0.0;
    for (int i = threadIdx.x; i < n; i += blockDim.x) {
        float v = in[i];
        s  += (double)v;
        s2 += (double)v * (double)v;
    }
    __shared__ double rs[32], rs2[32];
    __shared__ float smu, srs;
    int lane = threadIdx.x & 31, wid = threadIdx.x >> 5;
#pragma unroll
    for (int o = 16; o; o >>= 1) {
        s  += __shfl_xor_sync(0xffffffffu, s, o);
        s2 += __shfl_xor_sync(0xffffffffu, s2, o);
    }
    if (lane == 0) { rs[wid] = s; rs2[wid] = s2; }
    __syncthreads();
    if (threadIdx.x == 0) {
        int nw = blockDim.x >> 5;
        double ts = 0.0, ts2 = 0.0;
        for (int i = 0; i < nw; i++) { ts += rs[i]; ts2 += rs2[i]; }
        double mu  = ts / n;
        double var = ts2 / n - mu * mu;
        smu = (float)mu;
        srs = rsqrtf((float)var + 1e-5f);
    }
    __syncthreads();
    float mu = smu, r = srs;
    for (int i = threadIdx.x; i < n; i += blockDim.x)
        out[i] = (in[i] - mu) * r;
}

__global__ void ln_img_k(const float* __restrict__ in) {
    ln_block(in + (size_t)blockIdx.x * SD_, g_x + (size_t)blockIdx.x * SD_, SD_);
}
__global__ void ln_skip_k() {
    ln_block(g_skip + (size_t)blockIdx.x * SD_, g_y + (size_t)blockIdx.x * SD_, SD_);
}
__global__ void ln_head_k() {
    float* p = g_qkv + (size_t)blockIdx.x * SHD_;
    ln_block(p, p, SHD_);
}

// ---------------- QKV projection ----------------
// out[mat][b,h,s,e] = sum_d x[b,s,d] * w[mat][h][d,e]
// Block: 128 m x 64 e, BK = 16, 256 threads, thread = 8m x 4e (f32x2 over e).
__global__ void qkv_k(const float* __restrict__ w1,
                      const float* __restrict__ w2,
                      const float* __restrict__ w3) {
    const int m0  = blockIdx.x * 128;
    const int h   = blockIdx.y;
    const int mat = blockIdx.z;
    const float* w = (mat == 0 ? w1 : (mat == 1 ? w2 : w3)) + (size_t)h * (D_ * HD_);
    __shared__ float2 xs[128 * 16];   // [mm][kk] duplicated pairs (v,v)
    __shared__ float  ws[16 * 64];    // [kk][e]
    const int tid = threadIdx.x;
    const int tr = tid >> 4, tc = tid & 15;
    u64 acc[8][2];
#pragma unroll
    for (int i = 0; i < 8; i++) { acc[i][0] = 0ull; acc[i][1] = 0ull; }

    for (int k0 = 0; k0 < D_; k0 += 16) {
        __syncthreads();
#pragma unroll
        for (int i = 0; i < 8; i++) {
            int id = tid + i * 256;
            int kk = id & 15, mm = id >> 4;
            int m = m0 + mm;
            float v = (m < BS_) ? g_x[(size_t)m * D_ + k0 + kk] : 0.f;
            xs[mm * 16 + kk] = make_float2(v, v);
        }
#pragma unroll
        for (int i = 0; i < 4; i++) {
            int id = tid + i * 256;
            int kk = id >> 6, e = id & 63;
            ws[id] = w[(size_t)(k0 + kk) * HD_ + e];
        }
        __syncthreads();
#pragma unroll
        for (int kk = 0; kk < 16; kk++) {
            u64 b0 = *(const u64*)(ws + kk * 64 + tc * 4);
            u64 b1 = *(const u64*)(ws + kk * 64 + tc * 4 + 2);
#pragma unroll
            for (int i = 0; i < 8; i++) {
                u64 a = *((const u64*)xs + (tr * 8 + i) * 16 + kk);
                FMA2(acc[i][0], a, b0);
                FMA2(acc[i][1], a, b1);
            }
        }
    }
#pragma unroll
    for (int i = 0; i < 8; i++) {
        int m = m0 + tr * 8 + i;
        if (m < BS_) {
            int bb = m / S_, s = m % S_;
            float* op = g_qkv + ((size_t)(mat * BH_) + bb * H_ + h) * SHD_ + s * HD_ + tc * 4;
            float2 lo = unpack2(acc[i][0]);
            float2 hi = unpack2(acc[i][1]);
            float4 rr; rr.x = lo.x; rr.y = lo.y; rr.z = hi.x; rr.w = hi.y;
            *(float4*)op = rr;
        }
    }
}

// ---------------- Fused attention per (b,h), v2 ----------------
// 512 threads, 8 query rows per iteration, f32x2 scores.
#define KP_ 68
#define AT_THREADS 512
#define ATTN_SMEM_FLOATS (2 * S_ * KP_ + 512 + 1600 + 64 + 64 + 8 + 8 + 4096)
#define ATTN_SMEM_BYTES  (ATTN_SMEM_FLOATS * 4)

__global__ void __launch_bounds__(AT_THREADS, 1) attn_k() {
    extern __shared__ float sm[];
    float* Ks     = sm;                       // S*KP
    float* Vs     = Ks + S_ * KP_;            // S*KP
    float* qs     = Vs + S_ * KP_;            // 512 : [r][e]  (8 rows x 64)
    float* ps     = qs + 512;                 // 1600: [t][r]  (t*8 + r), t < 197
    float* rmax   = ps + 1600;                // 64  : [r][wid<7]
    float* rsum   = rmax + 64;                // 64
    float* rowmax = rsum + 64;                // 8
    float* rowsum = rowmax + 8;               // 8
    float* obuf   = rowsum + 8;               // 4096: [part][r][e]

    const int bh   = blockIdx.x;
    const int tid  = threadIdx.x;
    const int lane = tid & 31, wid = tid >> 5;
    const float* qg = g_qkv + (size_t)bh * SHD_;
    const float* kg = g_qkv + (size_t)(BH_ + bh) * SHD_;
    const float* vg = g_qkv + (size_t)(2 * BH_ + bh) * SHD_;

    for (int idx = tid; idx < SHD_; idx += AT_THREADS) {
        int t = idx >> 6, e = idx & 63;
        Ks[t * KP_ + e] = kg[idx];
        Vs[t * KP_ + e] = vg[idx];
    }
    const int bb = bh / H_, hh = bh % H_;
    const float scale = rsqrtf((float)S_);
    const float* xres = g_x + (size_t)bb * SD_;
    float* outp = g_skip + (size_t)bb * SD_;

    const int t = tid;   // key index for score phase

    for (int r0 = 0; r0 < S_; r0 += 8) {
        // load 8 query rows into qs[r*64 + e]
        {
            int r = tid >> 6, e = tid & 63;
            int row = r0 + r;
            qs[tid] = (row < S_) ? qg[row * HD_ + e] : 0.f;
        }
        __syncthreads();  // SYNC1 (also covers K/V load on first iter)

        // ---- scores: thread = key t, 8 rows, f32x2 ----
        float sc[8];
        {
            u64 acc[8];
#pragma unroll
            for (int r = 0; r < 8; r++) acc[r] = 0ull;
            if (t < S_) {
                const ulonglong2* kr = (const ulonglong2*)(Ks + t * KP_);
                const ulonglong2* q2 = (const ulonglong2*)qs;
#pragma unroll
                for (int ee = 0; ee < 16; ee++) {
                    ulonglong2 kv = kr[ee];
#pragma unroll
                    for (int r = 0; r < 8; r++) {
                        ulonglong2 qv = q2[r * 16 + ee];
                        FMA2(acc[r], kv.x, qv.x);
                        FMA2(acc[r], kv.y, qv.y);
                    }
                }
            }
#pragma unroll
            for (int r = 0; r < 8; r++) {
                float2 v = unpack2(acc[r]);
                sc[r] = (t < S_) ? (v.x + v.y) * scale : -1e30f;
            }
        }
        // ---- row maxima (warps 0..6 hold keys) ----
        if (wid < 7) {
#pragma unroll
            for (int r = 0; r < 8; r++) {
                float m = sc[r];
#pragma unroll
                for (int o = 16; o; o >>= 1)
                    m = fmaxf(m, __shfl_xor_sync(0xffffffffu, m, o));
                if (lane == 0) rmax[r * 8 + wid] = m;
            }
        }
        __syncthreads();  // SYNC2
        if (tid < 8) {
            float mm = -1e30f;
#pragma unroll
            for (int wq = 0; wq < 7; wq++) mm = fmaxf(mm, rmax[tid * 8 + wq]);
            rowmax[tid] = mm;
        }
        __syncthreads();  // SYNC3
        // ---- exp + store ps + row sums ----
        float ex[8];
#pragma unroll
        for (int r = 0; r < 8; r++)
            ex[r] = (t < S_) ? __expf(sc[r] - rowmax[r]) : 0.f;
        if (t < S_) {
            *(float4*)(ps + t * 8)     = make_float4(ex[0], ex[1], ex[2], ex[3]);
            *(float4*)(ps + t * 8 + 4) = make_float4(ex[4], ex[5], ex[6], ex[7]);
        }
        if (wid < 7) {
#pragma unroll
            for (int r = 0; r < 8; r++) {
                float s = ex[r];
#pragma unroll
                for (int o = 16; o; o >>= 1)
                    s += __shfl_xor_sync(0xffffffffu, s, o);
                if (lane == 0) rsum[r * 8 + wid] = s;
            }
        }
        __syncthreads();  // SYNC4
        if (tid < 8) {
            float ss = 0.f;
#pragma unroll
            for (int wq = 0; wq < 7; wq++) ss += rsum[tid * 8 + wq];
            rowsum[tid] = ss;
        }
        // ---- AV: thread = (part 0..7, e 0..63), t strided by 8 ----
        {
            int e = tid & 63, part = tid >> 6;
            float a[8];
#pragma unroll
            for (int r = 0; r < 8; r++) a[r] = 0.f;
            for (int tt = part; tt < S_; tt += 8) {
                float vv = Vs[tt * KP_ + e];
                float4 p0 = *(const float4*)(ps + tt * 8);
                float4 p1 = *(const float4*)(ps + tt * 8 + 4);
                a[0] += p0.x * vv; a[1] += p0.y * vv;
                a[2] += p0.z * vv; a[3] += p0.w * vv;
                a[4] += p1.x * vv; a[5] += p1.y * vv;
                a[6] += p1.z * vv; a[7] += p1.w * vv;
            }
#pragma unroll
            for (int r = 0; r < 8; r++) obuf[part * 512 + r * 64 + e] = a[r];
        }
        __syncthreads();  // SYNC5
        // ---- writeback with residual ----
        {
            int r = tid >> 6, e = tid & 63;
            int row = r0 + r;
            if (row < S_) {
                float o = 0.f;
#pragma unroll
                for (int part = 0; part < 8; part++)
                    o += obuf[part * 512 + r * 64 + e];
                o /= rowsum[r];
                int off = row * D_ + hh * HD_ + e;
                outp[off] = o + xres[off];
            }
        }
        // next iteration's SYNC1 separates writeback from shared rewrites
    }
}

// ---------------- transpose g_y -> g_yT ----------------
__global__ void transpose_k() {
    __shared__ float t[32][33];
    int k0 = blockIdx.x * 32;
    int tx = threadIdx.x & 31, ty = threadIdx.x >> 5;  // ty 0..7
#pragma unroll
    for (int i = 0; i < 4; i++) {
        int m = ty + 8 * i;
        t[m][tx] = g_y[(size_t)m * SD_ + k0 + tx];
    }
    __syncthreads();
#pragma unroll
    for (int i = 0; i < 4; i++) {
        int kk = ty + 8 * i;
        g_yT[(size_t)(k0 + kk) * 32 + tx] = t[tx][kk];
    }
}

// ---------------- MLP GEMM 1 (split-K partials), v2 ----------------
// C[32,1024] = y[32,SD] @ W1[SD,1024], K-chunk 384 per blockIdx.y.
// Block tile 32m x 128n, 256 threads.
// Thread: nn=tid&31 owns n {nn, nn+32, nn+64, nn+96}; mg=tid>>5 owns m-pairs {2mg, 2mg+1}.
// ws pre-duplicated as float2 -> no pack2 in the inner loop: 14 issues / 16 FMA-cycles.
__global__ void mlp1_k(const float* __restrict__ w1) {
    const int n0 = blockIdx.x * 128;
    const int kbase = blockIdx.y * KCH_;
    __shared__ float2 ws2[16 * 128];  // [kk][n] duplicated (v,v)
    __shared__ float2 xs[16 * 16];    // [kk][mpair]
    const int tid = threadIdx.x;
    const int nn = tid & 31;
    const int mg = tid >> 5;  // 0..7
    u64 acc[4][2];
#pragma unroll
    for (int j = 0; j < 4; j++) { acc[j][0] = 0ull; acc[j][1] = 0ull; }

    for (int k0 = 0; k0 < KCH_; k0 += 16) {
        __syncthreads();
#pragma unroll
        for (int i = 0; i < 8; i++) {
            int id = tid + i * 256;
            int kk = id >> 7, e = id & 127;
            float v = w1[(size_t)(kbase + k0 + kk) * HID_ + n0 + e];
            ws2[id] = make_float2(v, v);
        }
        {
            int kk = tid >> 4, mp = tid & 15;
            xs[tid] = ((const float2*)g_yT)[(size_t)(kbase + k0 + kk) * 16 + mp];
        }
        __syncthreads();
#pragma unroll
        for (int kk = 0; kk < 16; kk++) {
            u64 b0 = *((const u64*)ws2 + kk * 128 + nn);
            u64 b1 = *((const u64*)ws2 + kk * 128 + nn + 32);
            u64 b2 = *((const u64*)ws2 + kk * 128 + nn + 64);
            u64 b3 = *((const u64*)ws2 + kk * 128 + nn + 96);
            u64 a0 = *((const u64*)xs + kk * 16 + mg * 2);
            u64 a1 = *((const u64*)xs + kk * 16 + mg * 2 + 1);
            FMA2(acc[0][0], a0, b0); FMA2(acc[0][1], a1, b0);
            FMA2(acc[1][0], a0, b1); FMA2(acc[1][1], a1, b1);
            FMA2(acc[2][0], a0, b2); FMA2(acc[2][1], a1, b2);
            FMA2(acc[3][0], a0, b3); FMA2(acc[3][1], a1, b3);
        }
    }
    float* pp = g_part + (size_t)blockIdx.y * (B_ * HID_);
#pragma unroll
    for (int j = 0; j < 4; j++) {
        int n = n0 + nn + 32 * j;
#pragma unroll
        for (int i = 0; i < 2; i++) {
            float2 v = unpack2(acc[j][i]);
            int m = 2 * (mg * 2 + i);
            pp[(size_t)m * HID_ + n]       = v.x;
            pp[(size_t)(m + 1) * HID_ + n] = v.y;
        }
    }
}

// ---------------- reduce split-K + bias + GELU -> g_hT ----------------
__global__ void reduce1_k(const float* __restrict__ b1) {
    int idx = blockIdx.x * 256 + threadIdx.x;   // 0..32767
    float s = 0.f;
#pragma unroll 4
    for (int c = 0; c < SPLITK_; c++) s += g_part[(size_t)c * (B_ * HID_) + idx];
    int m = idx >> 10, j = idx & 1023;
    s += b1[j];
    float g = s * normcdff(s);
    g_hT[(size_t)j * 32 + m] = g;
}

// ---------------- MLP GEMM 2 + bias + GELU + skip ----------------
// out[32,SD] = skip + gelu(h[32,1024] @ W2[1024,SD] + b2)
// Block tile 32m x 128n. Thread: nn=tid&63 owns n {nn, nn+64}; mg=tid>>6 owns m-pairs mg*4..+3.
__global__ void mlp2_k(const float* __restrict__ w2, const float* __restrict__ b2,
                       float* __restrict__ out) {
    const int n0 = blockIdx.x * 128;
    __shared__ float  ws[16 * 128];
    __shared__ float2 xs[16 * 16];
    const int tid = threadIdx.x;
    const int nn = tid & 63;
    const int mg = tid >> 6;  // 0..3
    u64 acc[2][4];
#pragma unroll
    for (int j = 0; j < 2; j++)
#pragma unroll
        for (int i = 0; i < 4; i++) acc[j][i] = 0ull;

    for (int k0 = 0; k0 < HID_; k0 += 16) {
        __syncthreads();
#pragma unroll
        for (int i = 0; i < 8; i++) {
            int id = tid + i * 256;
            int kk = id >> 7, e = id & 127;
            ws[id] = w2[(size_t)(k0 + kk) * SD_ + n0 + e];
        }
        {
            int kk = tid >> 4, mp = tid & 15;
            xs[tid] = ((const float2*)g_hT)[(k0 + kk) * 16 + mp];
        }
        __syncthreads();
#pragma unroll
        for (int kk = 0; kk < 16; kk++) {
            float w0 = ws[kk * 128 + nn];
            float w1v = ws[kk * 128 + 64 + nn];
            u64 b0 = pack2(w0, w0);
            u64 b1 = pack2(w1v, w1v);
#pragma unroll
            for (int i = 0; i < 4; i++) {
                u64 a = *((const u64*)xs + kk * 16 + mg * 4 + i);
                FMA2(acc[0][i], a, b0);
                FMA2(acc[1][i], a, b1);
            }
        }
    }
#pragma unroll
    for (int j = 0; j < 2; j++) {
        int n = n0 + nn + 64 * j;
        float bias = b2[n];
#pragma unroll
        for (int i = 0; i < 4; i++) {
            float2 v = unpack2(acc[j][i]);
            int m = 2 * (mg * 4 + i);
            float s0 = v.x + bias, s1 = v.y + bias;
            float g0 = s0 * normcdff(s0);
            float g1 = s1 * normcdff(s1);
            out[(size_t)m * SD_ + n]       = g_skip[(size_t)m * SD_ + n] + g0;
            out[(size_t)(m + 1) * SD_ + n] = g_skip[(size_t)(m + 1) * SD_ + n] + g1;
        }
    }
}

// ---------------- launch ----------------
extern "C" void kernel_launch(void* const* d_in, const int* in_sizes, int n_in,
                              void* d_out, int out_size) {
    const float* images = (const float*)d_in[0];
    const float* w1     = (const float*)d_in[1];
    const float* w2     = (const float*)d_in[2];
    const float* w3     = (const float*)d_in[3];
    const float* mlp_w1 = (const float*)d_in[4];
    const float* mlp_b1 = (const float*)d_in[5];
    const float* mlp_w2 = (const float*)d_in[6];
    const float* mlp_b2 = (const float*)d_in[7];
    float* out = (float*)d_out;

    cudaFuncSetAttribute(attn_k, cudaFuncAttributeMaxDynamicSharedMemorySize,
                         ATTN_SMEM_BYTES);

    ln_img_k<<<B_, 512>>>(images);
    qkv_k<<<dim3(50, H_, 3), 256>>>(w1, w2, w3);
    ln_head_k<<<3 * BH_, 512>>>();
    attn_k<<<BH_, AT_THREADS, ATTN_SMEM_BYTES>>>();
    ln_skip_k<<<B_, 512>>>();
    transpose_k<<<SD_ / 32, 256>>>();
    mlp1_k<<<dim3(HID_ / 128, SPLITK_), 256>>>(mlp_w1);
    reduce1_k<<<(B_ * HID_) / 256, 256>>>(mlp_b1);
    mlp2_k<<<SD_ / 128, 256>>>(mlp_w2, mlp_b2, out);
}

// round 16
// speedup vs baseline: 1.0531x; 1.0379x over previous
#include <cuda_runtime.h>
#include <cuda_bf16.h>
#include <math.h>

typedef unsigned long long u64;

#define B_   32
#define S_   197
#define D_   384
#define H_   6
#define HD_  64
#define HID_ 1024
#define SD_  75648           // S*D
#define BS_  6304            // B*S
#define BH_  192             // B*H
#define SHD_ 12608           // S*HD
#define SPLITK_ 197
#define KCH_ 384             // SD / SPLITK

// ---------------- scratch (static device globals) ----------------
__device__ float g_x[B_ * SD_];             // LN(images)
__device__ float g_qkv[3 * BH_ * SHD_];     // [mat][b*H+h][s*HD+e]
__device__ float g_skip[B_ * SD_];          // attn out + residual
__device__ float g_y[B_ * SD_];             // LN(skip)
__device__ float g_yT[SD_ * B_];            // transposed y
__device__ float g_part[SPLITK_ * B_ * HID_];
__device__ float g_hT[HID_ * B_];           // gelu(y@W1+b1), transposed

// ---------------- packed f32x2 helpers ----------------
__device__ __forceinline__ u64 pack2(float a, float b) {
    u64 u;
    asm("mov.b64 %0, {%1, %2};" : "=l"(u) : "r"(__float_as_uint(a)), "r"(__float_as_uint(b)));
    return u;
}
__device__ __forceinline__ float2 unpack2(u64 u) {
    unsigned int lo, hi;
    asm("mov.b64 {%0, %1}, %2;" : "=r"(lo), "=r"(hi) : "l"(u));
    return make_float2(__uint_as_float(lo), __uint_as_float(hi));
}
#define FMA2(d, a, b) asm("fma.rn.f32x2 %0, %1, %2, %0;" : "+l"(d) : "l"(a), "l"(b))

// ---------------- LayerNorm over a contiguous slab ----------------
__device__ __forceinline__ void ln_block(const float* __restrict__ in,
                                         float* __restrict__ out, int n) {
    double s = 0.0, s2 = 0.0;
    for (int i = threadIdx.x; i < n; i += blockDim.x) {
        float v = in[i];
        s  += (double)v;
        s2 += (double)v * (double)v;
    }
    __shared__ double rs[32], rs2[32];
    __shared__ float smu, srs;
    int lane = threadIdx.x & 31, wid = threadIdx.x >> 5;
#pragma unroll
    for (int o = 16; o; o >>= 1) {
        s  += __shfl_xor_sync(0xffffffffu, s, o);
        s2 += __shfl_xor_sync(0xffffffffu, s2, o);
    }
    if (lane == 0) { rs[wid] = s; rs2[wid] = s2; }
    __syncthreads();
    if (threadIdx.x == 0) {
        int nw = blockDim.x >> 5;
        double ts = 0.0, ts2 = 0.0;
        for (int i = 0; i < nw; i++) { ts += rs[i]; ts2 += rs2[i]; }
        double mu  = ts / n;
        double var = ts2 / n - mu * mu;
        smu = (float)mu;
        srs = rsqrtf((float)var + 1e-5f);
    }
    __syncthreads();
    float mu = smu, r = srs;
    for (int i = threadIdx.x; i < n; i += blockDim.x)
        out[i] = (in[i] - mu) * r;
}

__global__ void ln_img_k(const float* __restrict__ in) {
    ln_block(in + (size_t)blockIdx.x * SD_, g_x + (size_t)blockIdx.x * SD_, SD_);
}
__global__ void ln_skip_k() {
    ln_block(g_skip + (size_t)blockIdx.x * SD_, g_y + (size_t)blockIdx.x * SD_, SD_);
}
__global__ void ln_head_k() {
    float* p = g_qkv + (size_t)blockIdx.x * SHD_;
    ln_block(p, p, SHD_);
}

// ---------------- QKV projection, v3 ----------------
// Block 128m x 64e, BK=16, 128 threads; thread = 8m x 8e (4 u64) -> pipe-bound.
__global__ void qkv_k(const float* __restrict__ w1,
                      const float* __restrict__ w2,
                      const float* __restrict__ w3) {
    const int m0  = blockIdx.x * 128;
    const int h   = blockIdx.y;
    const int mat = blockIdx.z;
    const float* w = (mat == 0 ? w1 : (mat == 1 ? w2 : w3)) + (size_t)h * (D_ * HD_);
    __shared__ float2 xs[128 * 16];   // [mm][kk] duplicated pairs (v,v)
    __shared__ float  ws[16 * 64];    // [kk][e]
    const int tid = threadIdx.x;
    const int tr = tid >> 3;          // 0..15 -> m rows tr*8..tr*8+7
    const int tc = tid & 7;           // 0..7  -> e cols tc*8..tc*8+7
    u64 acc[8][4];
#pragma unroll
    for (int i = 0; i < 8; i++)
#pragma unroll
        for (int j = 0; j < 4; j++) acc[i][j] = 0ull;

    for (int k0 = 0; k0 < D_; k0 += 16) {
        __syncthreads();
#pragma unroll
        for (int i = 0; i < 16; i++) {
            int id = tid + i * 128;
            int kk = id & 15, mm = id >> 4;
            int m = m0 + mm;
            float v = (m < BS_) ? g_x[(size_t)m * D_ + k0 + kk] : 0.f;
            xs[mm * 16 + kk] = make_float2(v, v);
        }
#pragma unroll
        for (int i = 0; i < 8; i++) {
            int id = tid + i * 128;
            int kk = id >> 6, e = id & 63;
            ws[id] = w[(size_t)(k0 + kk) * HD_ + e];
        }
        __syncthreads();
#pragma unroll
        for (int kk = 0; kk < 16; kk++) {
            const ulonglong2* bp = (const ulonglong2*)(ws + kk * 64 + tc * 8);
            ulonglong2 b01 = bp[0];
            ulonglong2 b23 = bp[1];
#pragma unroll
            for (int i = 0; i < 8; i++) {
                u64 a = *((const u64*)xs + (tr * 8 + i) * 16 + kk);
                FMA2(acc[i][0], a, b01.x);
                FMA2(acc[i][1], a, b01.y);
                FMA2(acc[i][2], a, b23.x);
                FMA2(acc[i][3], a, b23.y);
            }
        }
    }
#pragma unroll
    for (int i = 0; i < 8; i++) {
        int m = m0 + tr * 8 + i;
        if (m < BS_) {
            int bb = m / S_, s = m % S_;
            float* op = g_qkv + ((size_t)(mat * BH_) + bb * H_ + h) * SHD_ + s * HD_ + tc * 8;
            float2 v0 = unpack2(acc[i][0]);
            float2 v1 = unpack2(acc[i][1]);
            float2 v2 = unpack2(acc[i][2]);
            float2 v3 = unpack2(acc[i][3]);
            float4 r0; r0.x = v0.x; r0.y = v0.y; r0.z = v1.x; r0.w = v1.y;
            float4 r1; r1.x = v2.x; r1.y = v2.y; r1.z = v3.x; r1.w = v3.y;
            *(float4*)op       = r0;
            *(float4*)(op + 4) = r1;
        }
    }
}

// ---------------- Fused attention, v3 ----------------
// 2 blocks per (b,h): query halves. Score phase: warp-per-key-stride-16,
// lane = (r 0..7, eq 0..3); q in registers; butterfly over eq.
#define KP_ 68
#define AT_THREADS 512
#define ATTN_SMEM_FLOATS (2 * S_ * KP_ + 512 + 1600 + 128 + 64 + 8 + 8 + 4096)
#define ATTN_SMEM_BYTES  (ATTN_SMEM_FLOATS * 4)

__global__ void __launch_bounds__(AT_THREADS, 1) attn_k() {
    extern __shared__ float sm[];
    float* Ks     = sm;                       // S*KP
    float* Vs     = Ks + S_ * KP_;            // S*KP
    float* qs     = Vs + S_ * KP_;            // 512 : [r][e]
    float* ps     = qs + 512;                 // 1600: [t][r] (t*8+r)
    float* rmax   = ps + 1600;                // 128 : [r][warp]
    float* rsum   = rmax + 128;               // 64  : [r][wid<7]
    float* rowmax = rsum + 64;                // 8
    float* rowsum = rowmax + 8;               // 8
    float* obuf   = rowsum + 8;               // 4096: [part][r][e]

    const int bh   = blockIdx.x >> 1;
    const int half = blockIdx.x & 1;
    const int tid  = threadIdx.x;
    const int lane = tid & 31, wid = tid >> 5;
    const float* qg = g_qkv + (size_t)bh * SHD_;
    const float* kg = g_qkv + (size_t)(BH_ + bh) * SHD_;
    const float* vg = g_qkv + (size_t)(2 * BH_ + bh) * SHD_;

    for (int idx = tid; idx < SHD_; idx += AT_THREADS) {
        int t = idx >> 6, e = idx & 63;
        Ks[t * KP_ + e] = kg[idx];
        Vs[t * KP_ + e] = vg[idx];
    }
    const int bb = bh / H_, hh = bh % H_;
    const float scale = rsqrtf((float)S_);
    const float* xres = g_x + (size_t)bb * SD_;
    float* outp = g_skip + (size_t)bb * SD_;

    const int r_begin = half ? 100 : 0;
    const int r_end   = half ? S_ : 100;
    const int rl = lane >> 2;    // row 0..7 (score phase)
    const int eq = lane & 3;     // e-quad 0..3

    for (int r0 = r_begin; r0 < r_end; r0 += 8) {
        // load 8 query rows into qs[r*64 + e]
        {
            int r = tid >> 6, e = tid & 63;
            int row = r0 + r;
            qs[tid] = (row < S_) ? qg[row * HD_ + e] : 0.f;
        }
        __syncthreads();  // SYNC1

        // ---- pass A: raw scores + running max ----
        {
            u64 qr[8];
            const ulonglong2* qp = (const ulonglong2*)(qs + rl * 64 + eq * 16);
            ulonglong2 q0 = qp[0], q1 = qp[1], q2 = qp[2], q3 = qp[3];
            qr[0] = q0.x; qr[1] = q0.y; qr[2] = q1.x; qr[3] = q1.y;
            qr[4] = q2.x; qr[5] = q2.y; qr[6] = q3.x; qr[7] = q3.y;
            float mrun = -1e30f;
            for (int t = wid; t < S_; t += 16) {
                const ulonglong2* kp = (const ulonglong2*)(Ks + t * KP_ + eq * 16);
                ulonglong2 k0 = kp[0], k1 = kp[1], k2 = kp[2], k3 = kp[3];
                u64 acc = 0ull;
                FMA2(acc, k0.x, qr[0]); FMA2(acc, k0.y, qr[1]);
                FMA2(acc, k1.x, qr[2]); FMA2(acc, k1.y, qr[3]);
                FMA2(acc, k2.x, qr[4]); FMA2(acc, k2.y, qr[5]);
                FMA2(acc, k3.x, qr[6]); FMA2(acc, k3.y, qr[7]);
                float2 v = unpack2(acc);
                float sc = v.x + v.y;
                sc += __shfl_xor_sync(0xffffffffu, sc, 1);
                sc += __shfl_xor_sync(0xffffffffu, sc, 2);
                sc *= scale;
                if (eq == 0) ps[t * 8 + rl] = sc;
                mrun = fmaxf(mrun, sc);
            }
            if (eq == 0) rmax[rl * 16 + wid] = mrun;
        }
        __syncthreads();  // SYNC2
        if (tid < 8) {
            float mm = -1e30f;
#pragma unroll
            for (int wq = 0; wq < 16; wq++) mm = fmaxf(mm, rmax[tid * 16 + wq]);
            rowmax[tid] = mm;
        }
        __syncthreads();  // SYNC3
        // ---- exp pass (thread = key t) + row sums ----
        {
            int t = tid;
            float ex[8];
            if (t < S_) {
                float4 p0 = *(const float4*)(ps + t * 8);
                float4 p1 = *(const float4*)(ps + t * 8 + 4);
                ex[0] = __expf(p0.x - rowmax[0]); ex[1] = __expf(p0.y - rowmax[1]);
                ex[2] = __expf(p0.z - rowmax[2]); ex[3] = __expf(p0.w - rowmax[3]);
                ex[4] = __expf(p1.x - rowmax[4]); ex[5] = __expf(p1.y - rowmax[5]);
                ex[6] = __expf(p1.z - rowmax[6]); ex[7] = __expf(p1.w - rowmax[7]);
                *(float4*)(ps + t * 8)     = make_float4(ex[0], ex[1], ex[2], ex[3]);
                *(float4*)(ps + t * 8 + 4) = make_float4(ex[4], ex[5], ex[6], ex[7]);
            } else {
#pragma unroll
                for (int r = 0; r < 8; r++) ex[r] = 0.f;
            }
            if (wid < 7) {
#pragma unroll
                for (int r = 0; r < 8; r++) {
                    float s = ex[r];
#pragma unroll
                    for (int o = 16; o; o >>= 1)
                        s += __shfl_xor_sync(0xffffffffu, s, o);
                    if (lane == 0) rsum[r * 8 + wid] = s;
                }
            }
        }
        __syncthreads();  // SYNC4
        if (tid < 8) {
            float ss = 0.f;
#pragma unroll
            for (int wq = 0; wq < 7; wq++) ss += rsum[tid * 8 + wq];
            rowsum[tid] = ss;
        }
        // ---- AV: thread = (part 0..7, e 0..63) ----
        {
            int e = tid & 63, part = tid >> 6;
            float a[8];
#pragma unroll
            for (int r = 0; r < 8; r++) a[r] = 0.f;
            for (int tt = part; tt < S_; tt += 8) {
                float vv = Vs[tt * KP_ + e];
                float4 p0 = *(const float4*)(ps + tt * 8);
                float4 p1 = *(const float4*)(ps + tt * 8 + 4);
                a[0] += p0.x * vv; a[1] += p0.y * vv;
                a[2] += p0.z * vv; a[3] += p0.w * vv;
                a[4] += p1.x * vv; a[5] += p1.y * vv;
                a[6] += p1.z * vv; a[7] += p1.w * vv;
            }
#pragma unroll
            for (int r = 0; r < 8; r++) obuf[part * 512 + r * 64 + e] = a[r];
        }
        __syncthreads();  // SYNC5
        // ---- writeback with residual ----
        {
            int r = tid >> 6, e = tid & 63;
            int row = r0 + r;
            if (row < S_) {
                float o = 0.f;
#pragma unroll
                for (int part = 0; part < 8; part++)
                    o += obuf[part * 512 + r * 64 + e];
                o /= rowsum[r];
                int off = row * D_ + hh * HD_ + e;
                outp[off] = o + xres[off];
            }
        }
        // next iteration's SYNC1 separates writeback/ps reuse
    }
}

// ---------------- transpose g_y -> g_yT ----------------
__global__ void transpose_k() {
    __shared__ float t[32][33];
    int k0 = blockIdx.x * 32;
    int tx = threadIdx.x & 31, ty = threadIdx.x >> 5;  // ty 0..7
#pragma unroll
    for (int i = 0; i < 4; i++) {
        int m = ty + 8 * i;
        t[m][tx] = g_y[(size_t)m * SD_ + k0 + tx];
    }
    __syncthreads();
#pragma unroll
    for (int i = 0; i < 4; i++) {
        int kk = ty + 8 * i;
        g_yT[(size_t)(k0 + kk) * 32 + tx] = t[tx][kk];
    }
}

// ---------------- MLP GEMM 1 (split-K partials), v3 ----------------
// Block 32m x 128n, BK=16, 128 threads; thread = (nn 0..31) x (mg 0..3),
// 4 n x 4 m-pairs. Plain weights + pack2 (ALU pipe) -> pipe-bound.
__global__ void mlp1_k(const float* __restrict__ w1) {
    const int n0 = blockIdx.x * 128;
    const int kbase = blockIdx.y * KCH_;
    __shared__ float  ws[16 * 128];   // [kk][n]
    __shared__ float2 xs[16 * 16];    // [kk][mpair]
    const int tid = threadIdx.x;
    const int nn = tid & 31;
    const int mg = tid >> 5;  // 0..3 -> m-pairs mg*4..mg*4+3
    u64 acc[4][4];
#pragma unroll
    for (int j = 0; j < 4; j++)
#pragma unroll
        for (int i = 0; i < 4; i++) acc[j][i] = 0ull;

    for (int k0 = 0; k0 < KCH_; k0 += 16) {
        __syncthreads();
#pragma unroll
        for (int i = 0; i < 16; i++) {
            int id = tid + i * 128;
            int kk = id >> 7, e = id & 127;
            ws[id] = w1[(size_t)(kbase + k0 + kk) * HID_ + n0 + e];
        }
#pragma unroll
        for (int i = 0; i < 2; i++) {
            int id = tid + i * 128;
            int kk = id >> 4, mp = id & 15;
            xs[id] = ((const float2*)g_yT)[(size_t)(kbase + k0 + kk) * 16 + mp];
        }
        __syncthreads();
#pragma unroll
        for (int kk = 0; kk < 16; kk++) {
            float w0 = ws[kk * 128 + nn];
            float w1v = ws[kk * 128 + 32 + nn];
            float w2v = ws[kk * 128 + 64 + nn];
            float w3v = ws[kk * 128 + 96 + nn];
            u64 b0 = pack2(w0, w0);
            u64 b1 = pack2(w1v, w1v);
            u64 b2 = pack2(w2v, w2v);
            u64 b3 = pack2(w3v, w3v);
#pragma unroll
            for (int i = 0; i < 4; i++) {
                u64 a = *((const u64*)xs + kk * 16 + mg * 4 + i);
                FMA2(acc[0][i], a, b0);
                FMA2(acc[1][i], a, b1);
                FMA2(acc[2][i], a, b2);
                FMA2(acc[3][i], a, b3);
            }
        }
    }
    float* pp = g_part + (size_t)blockIdx.y * (B_ * HID_);
#pragma unroll
    for (int j = 0; j < 4; j++) {
        int n = n0 + nn + 32 * j;
#pragma unroll
        for (int i = 0; i < 4; i++) {
            float2 v = unpack2(acc[j][i]);
            int m = 2 * (mg * 4 + i);
            pp[(size_t)m * HID_ + n]       = v.x;
            pp[(size_t)(m + 1) * HID_ + n] = v.y;
        }
    }
}

// ---------------- reduce split-K + bias + GELU -> g_hT ----------------
__global__ void reduce1_k(const float* __restrict__ b1) {
    int idx = blockIdx.x * 256 + threadIdx.x;   // 0..32767
    float s = 0.f;
#pragma unroll 4
    for (int c = 0; c < SPLITK_; c++) s += g_part[(size_t)c * (B_ * HID_) + idx];
    int m = idx >> 10, j = idx & 1023;
    s += b1[j];
    float g = s * normcdff(s);
    g_hT[(size_t)j * 32 + m] = g;
}

// ---------------- MLP GEMM 2 + bias + GELU + skip ----------------
__global__ void mlp2_k(const float* __restrict__ w2, const float* __restrict__ b2,
                       float* __restrict__ out) {
    const int n0 = blockIdx.x * 128;
    __shared__ float  ws[16 * 128];
    __shared__ float2 xs[16 * 16];
    const int tid = threadIdx.x;
    const int nn = tid & 63;
    const int mg = tid >> 6;  // 0..3
    u64 acc[2][4];
#pragma unroll
    for (int j = 0; j < 2; j++)
#pragma unroll
        for (int i = 0; i < 4; i++) acc[j][i] = 0ull;

    for (int k0 = 0; k0 < HID_; k0 += 16) {
        __syncthreads();
#pragma unroll
        for (int i = 0; i < 8; i++) {
            int id = tid + i * 256;
            int kk = id >> 7, e = id & 127;
            ws[id] = w2[(size_t)(k0 + kk) * SD_ + n0 + e];
        }
        {
            int kk = tid >> 4, mp = tid & 15;
            xs[tid] = ((const float2*)g_hT)[(k0 + kk) * 16 + mp];
        }
        __syncthreads();
#pragma unroll
        for (int kk = 0; kk < 16; kk++) {
            float w0 = ws[kk * 128 + nn];
            float w1v = ws[kk * 128 + 64 + nn];
            u64 b0 = pack2(w0, w0);
            u64 b1 = pack2(w1v, w1v);
#pragma unroll
            for (int i = 0; i < 4; i++) {
                u64 a = *((const u64*)xs + kk * 16 + mg * 4 + i);
                FMA2(acc[0][i], a, b0);
                FMA2(acc[1][i], a, b1);
            }
        }
    }
#pragma unroll
    for (int j = 0; j < 2; j++) {
        int n = n0 + nn + 64 * j;
        float bias = b2[n];
#pragma unroll
        for (int i = 0; i < 4; i++) {
            float2 v = unpack2(acc[j][i]);
            int m = 2 * (mg * 4 + i);
            float s0 = v.x + bias, s1 = v.y + bias;
            float g0 = s0 * normcdff(s0);
            float g1 = s1 * normcdff(s1);
            out[(size_t)m * SD_ + n]       = g_skip[(size_t)m * SD_ + n] + g0;
            out[(size_t)(m + 1) * SD_ + n] = g_skip[(size_t)(m + 1) * SD_ + n] + g1;
        }
    }
}

// ---------------- launch ----------------
extern "C" void kernel_launch(void* const* d_in, const int* in_sizes, int n_in,
                              void* d_out, int out_size) {
    const float* images = (const float*)d_in[0];
    const float* w1     = (const float*)d_in[1];
    const float* w2     = (const float*)d_in[2];
    const float* w3     = (const float*)d_in[3];
    const float* mlp_w1 = (const float*)d_in[4];
    const float* mlp_b1 = (const float*)d_in[5];
    const float* mlp_w2 = (const float*)d_in[6];
    const float* mlp_b2 = (const float*)d_in[7];
    float* out = (float*)d_out;

    cudaFuncSetAttribute(attn_k, cudaFuncAttributeMaxDynamicSharedMemorySize,
                         ATTN_SMEM_BYTES);

    ln_img_k<<<B_, 1024>>>(images);
    qkv_k<<<dim3(50, H_, 3), 128>>>(w1, w2, w3);
    ln_head_k<<<3 * BH_, 512>>>();
    attn_k<<<2 * BH_, AT_THREADS, ATTN_SMEM_BYTES>>>();
    ln_skip_k<<<B_, 1024>>>();
    transpose_k<<<SD_ / 32, 256>>>();
    mlp1_k<<<dim3(HID_ / 128, SPLITK_), 128>>>(mlp_w1);
    reduce1_k<<<(B_ * HID_) / 256, 256>>>(mlp_b1);
    mlp2_k<<<SD_ / 128, 256>>>(mlp_w2, mlp_b2, out);
}